// round 4
// baseline (speedup 1.0000x reference)
#include <cuda_runtime.h>
#include <cuda_bf16.h>
#include <mma.h>
#include <cstdint>
using namespace nvcuda;

#define N_NODES   50000
#define EMB       320
#define HID       64
#define NH        128
#define N_EDGES   400000

#define AP 40    // A smem pitch (bf16 elems), padded vs 32 to dodge conflicts
#define BP 136   // B smem pitch

// Scratch (no allocations allowed)
__device__ __align__(16) float g_P[N_NODES * NH];
__device__ __align__(16) float g_cvec[HID];
__device__ int g_idx64;

// ---------------------------------------------------------------------------
// Kernel 0: detect edge_index element width (int32 vs int64, little-endian).
// int64 viewed as int32 words -> odd words all zero; int32 -> random ids.
// ---------------------------------------------------------------------------
__global__ void detect_kernel(const int* __restrict__ ei_raw) {
    int is64 = 1;
    #pragma unroll
    for (int i = 0; i < 32; i++)
        if (ei_raw[2 * i + 1] != 0) { is64 = 0; break; }
    g_idx64 = is64;
}

// ---------------------------------------------------------------------------
// Kernel 1: bf16 3-term split GEMM via wmma (legacy HMMA; valid on compute_103).
//   P[v,0:64]  = embed[v] @ W1[0:320,:]
//   P[v,64:128]= embed[v] @ W1[320:640,:]
// Block tile 128x128, K in 10 chunks of 32. 8 warps: warp tile 64x32 (4x2 wmma).
// A,B split into (hi,lo) bf16; acc += Ah*Bh + Ah*Bl + Al*Bh  (fp32 accum).
// ---------------------------------------------------------------------------
__global__ __launch_bounds__(256) void gemm_kernel(const float* __restrict__ embed,
                                                   const float* __restrict__ W1) {
    __shared__ __nv_bfloat16 Ah[128][AP], Al[128][AP];
    __shared__ __nv_bfloat16 Bh[32][BP],  Bl[32][BP];

    const int tid = threadIdx.x;
    const int wid = tid >> 5;
    const int warp_m = wid & 1;     // 0..1 -> rows 0/64
    const int warp_n = wid >> 1;    // 0..3 -> cols *32
    const int m0 = blockIdx.x * 128;

    wmma::fragment<wmma::accumulator, 16, 16, 16, float> acc[4][2];
    #pragma unroll
    for (int i = 0; i < 4; i++)
        #pragma unroll
        for (int j = 0; j < 2; j++)
            wmma::fill_fragment(acc[i][j], 0.f);

    for (int k0 = 0; k0 < EMB; k0 += 32) {
        // ---- A chunk: 128 rows x 32 k, fp32 -> (hi, lo) bf16 ----
        for (int it = tid; it < 128 * 8; it += 256) {
            int r = it >> 3, q = it & 7;             // q-th float4 of 32-k strip
            int gm = m0 + r;
            float4 v = make_float4(0.f, 0.f, 0.f, 0.f);
            if (gm < N_NODES)
                v = *reinterpret_cast<const float4*>(&embed[(size_t)gm * EMB + k0 + q * 4]);
            float a[4] = {v.x, v.y, v.z, v.w};
            __nv_bfloat16 h[4], l[4];
            #pragma unroll
            for (int i = 0; i < 4; i++) {
                h[i] = __float2bfloat16(a[i]);
                l[i] = __float2bfloat16(a[i] - __bfloat162float(h[i]));
            }
            *reinterpret_cast<uint2*>(&Ah[r][q * 4]) = *reinterpret_cast<uint2*>(h);
            *reinterpret_cast<uint2*>(&Al[r][q * 4]) = *reinterpret_cast<uint2*>(l);
        }
        // ---- B chunk: Bs[k][half*64+j] = W1[(half*320 + k0 + k)*64 + j] ----
        for (int it = tid; it < 1024; it += 256) {
            int j4 = it & 15, half = (it >> 4) & 1, k = it >> 5;    // k: 0..31
            float4 v = *reinterpret_cast<const float4*>(&W1[(half * 320 + k0 + k) * 64 + j4 * 4]);
            float b[4] = {v.x, v.y, v.z, v.w};
            __nv_bfloat16 h[4], l[4];
            #pragma unroll
            for (int i = 0; i < 4; i++) {
                h[i] = __float2bfloat16(b[i]);
                l[i] = __float2bfloat16(b[i] - __bfloat162float(h[i]));
            }
            *reinterpret_cast<uint2*>(&Bh[k][half * 64 + j4 * 4]) = *reinterpret_cast<uint2*>(h);
            *reinterpret_cast<uint2*>(&Bl[k][half * 64 + j4 * 4]) = *reinterpret_cast<uint2*>(l);
        }
        __syncthreads();

        #pragma unroll
        for (int ks = 0; ks < 2; ks++) {
            wmma::fragment<wmma::matrix_b, 16, 16, 16, __nv_bfloat16, wmma::row_major> bh[2], bl[2];
            #pragma unroll
            for (int j = 0; j < 2; j++) {
                wmma::load_matrix_sync(bh[j], &Bh[ks * 16][warp_n * 32 + j * 16], BP);
                wmma::load_matrix_sync(bl[j], &Bl[ks * 16][warp_n * 32 + j * 16], BP);
            }
            #pragma unroll
            for (int i = 0; i < 4; i++) {
                wmma::fragment<wmma::matrix_a, 16, 16, 16, __nv_bfloat16, wmma::row_major> fah, fal;
                wmma::load_matrix_sync(fah, &Ah[warp_m * 64 + i * 16][ks * 16], AP);
                wmma::load_matrix_sync(fal, &Al[warp_m * 64 + i * 16][ks * 16], AP);
                #pragma unroll
                for (int j = 0; j < 2; j++) {
                    wmma::mma_sync(acc[i][j], fah, bh[j], acc[i][j]);
                    wmma::mma_sync(acc[i][j], fah, bl[j], acc[i][j]);
                    wmma::mma_sync(acc[i][j], fal, bh[j], acc[i][j]);
                }
            }
        }
        __syncthreads();
    }

    // ---- epilogue: fp32 accumulators -> g_P (row tiles of 16; 50000 % 16 == 0-safe per tile) ----
    #pragma unroll
    for (int i = 0; i < 4; i++) {
        int gm = m0 + warp_m * 64 + i * 16;
        if (gm < N_NODES) {
            #pragma unroll
            for (int j = 0; j < 2; j++)
                wmma::store_matrix_sync(&g_P[(size_t)gm * NH + warp_n * 32 + j * 16],
                                        acc[i][j], NH, wmma::mem_row_major);
        }
    }
}

// ---------------------------------------------------------------------------
// Kernel 2: cvec[j] = b1[j] + embed[node_id] @ W1[640:960, j]   (exact fp32)
// ---------------------------------------------------------------------------
__global__ void cvec_kernel(const float* __restrict__ embed,
                            const float* __restrict__ W1,
                            const float* __restrict__ b1,
                            const int*   __restrict__ nid) {
    int j = threadIdx.x;
    int n = nid[0];
    const float* er = &embed[(size_t)n * EMB];
    float s = b1[j];
    #pragma unroll 4
    for (int k = 0; k < EMB; k++)
        s = fmaf(er[k], W1[(640 + k) * 64 + j], s);
    g_cvec[j] = s;
}

// ---------------------------------------------------------------------------
// Kernel 3: per-edge gate. 16 lanes per edge (2 edges/warp), float4 loads,
// grid-stride with cvec/W2 cached in registers.
// ---------------------------------------------------------------------------
__global__ __launch_bounds__(256) void edge_kernel(const void* __restrict__ ei_raw,
                                                   const float* __restrict__ eps,
                                                   const float* __restrict__ W2,
                                                   const float* __restrict__ b2,
                                                   const float* __restrict__ tmp,
                                                   float* __restrict__ out) {
    const int lane = threadIdx.x & 31;
    const int sub  = lane >> 4;           // which edge of the pair
    const int j    = lane & 15;           // 16 lanes cover 64 floats via float4
    const int warpGlobal = (blockIdx.x * blockDim.x + threadIdx.x) >> 5;
    const int nWarps = (gridDim.x * blockDim.x) >> 5;

    const float4 cv = *reinterpret_cast<const float4*>(&g_cvec[j * 4]);
    const float4 w2 = *reinterpret_cast<const float4*>(&W2[j * 4]);
    const float  b2v = b2[0];
    const float  inv_tmp = 1.f / tmp[0];
    const int    is64 = g_idx64;
    const long long* e64 = (const long long*)ei_raw;
    const int*       e32 = (const int*)ei_raw;

    for (int e = warpGlobal * 2 + sub; e < N_EDGES; e += nWarps * 2) {
        int col, row;
        if (is64) { col = (int)e64[e]; row = (int)e64[N_EDGES + e]; }
        else      { col = e32[e];      row = e32[N_EDGES + e]; }

        float4 pc = *reinterpret_cast<const float4*>(&g_P[(size_t)col * NH + j * 4]);
        float4 pr = *reinterpret_cast<const float4*>(&g_P[(size_t)row * NH + 64 + j * 4]);

        float h0 = fmaxf(pc.x + pr.x + cv.x, 0.f);
        float h1 = fmaxf(pc.y + pr.y + cv.y, 0.f);
        float h2 = fmaxf(pc.z + pr.z + cv.z, 0.f);
        float h3 = fmaxf(pc.w + pr.w + cv.w, 0.f);

        float p = fmaf(h0, w2.x, fmaf(h1, w2.y, fmaf(h2, w2.z, h3 * w2.w)));
        #pragma unroll
        for (int o = 8; o > 0; o >>= 1)
            p += __shfl_xor_sync(0xffffffffu, p, o);

        if (j == 0) {
            float w    = p + b2v;
            const float bias = 0.0001f;
            float ev   = eps[e] * (1.f - 2.f * bias) + bias;
            float gate = (logf(ev) - log1pf(-ev) + w) * inv_tmp;
            out[e]     = 1.f / (1.f + expf(-gate));
        }
    }
}

// ---------------------------------------------------------------------------
// Inputs: 0:x 1:embed 2:edge_index 3:node_id 4:tmp 5:eps 6:W1 7:b1 8:W2 9:b2
// ---------------------------------------------------------------------------
extern "C" void kernel_launch(void* const* d_in, const int* in_sizes, int n_in,
                              void* d_out, int out_size) {
    const float* embed = (const float*)d_in[1];
    const void*  ei    = d_in[2];
    const int*   nid   = (const int*)d_in[3];
    const float* tmp   = (const float*)d_in[4];
    const float* eps   = (const float*)d_in[5];
    const float* W1    = (const float*)d_in[6];
    const float* b1    = (const float*)d_in[7];
    const float* W2    = (const float*)d_in[8];
    const float* b2    = (const float*)d_in[9];
    float* out = (float*)d_out;

    detect_kernel<<<1, 1>>>((const int*)ei);
    gemm_kernel<<<(N_NODES + 127) / 128, 256>>>(embed, W1);
    cvec_kernel<<<1, 64>>>(embed, W1, b1, nid);
    edge_kernel<<<1184, 256>>>(ei, eps, W2, b2, tmp, out);
}

// round 5
// speedup vs baseline: 1.2565x; 1.2565x over previous
#include <cuda_runtime.h>
#include <cstdint>

#define N_NODES   50000
#define EMB       320
#define HID       64
#define NH        128
#define N_EDGES   400000
#define BK        16
#define NCHUNK    (EMB / BK)   // 20

// Scratch (no allocations allowed)
__device__ __align__(16) float g_P[N_NODES * NH];
__device__ __align__(16) float g_cvec[HID];
__device__ int g_idx64;

// ---------------------------------------------------------------------------
// Kernel 0: detect edge_index element width (int32 vs int64, little-endian).
// ---------------------------------------------------------------------------
__global__ void detect_kernel(const int* __restrict__ ei_raw) {
    int is64 = 1;
    #pragma unroll
    for (int i = 0; i < 32; i++)
        if (ei_raw[2 * i + 1] != 0) { is64 = 0; break; }
    g_idx64 = is64;
}

// ---------------------------------------------------------------------------
// Kernel 1: fp32 SGEMM, tuned for FFMA issue-slot fraction.
//   P[v,0:64]  = embed[v] @ W1[0:320,:]
//   P[v,64:128]= embed[v] @ W1[320:640,:]
// Block 128x128, 256 thr, warp tile 32x64, micro 8x8 (4+4 split), BK=16,
// register-prefetch double buffering of global loads.
// ---------------------------------------------------------------------------
__global__ __launch_bounds__(256, 2) void gemm_kernel(const float* __restrict__ embed,
                                                      const float* __restrict__ W1) {
    __shared__ float As[BK][128];   // [k][m]
    __shared__ float Bs[BK][128];   // [k][n]

    const int tid  = threadIdx.x;
    const int wid  = tid >> 5;
    const int lane = tid & 31;
    const int wm   = wid & 3;        // warp row   -> m offset wm*32
    const int wn   = wid >> 2;       // warp col   -> n offset wn*64
    const int tm   = lane & 3;       // thread row -> +tm*4 (and +16)
    const int tn   = lane >> 2;      // thread col -> +tn*4 (and +32)
    const int m0   = blockIdx.x * 128;

    // A loader mapping: m = tid>>1 (0..127), k-half = (tid&1)*8
    const int am = tid >> 1;
    const int ak = (tid & 1) * 8;
    const int a_gm = m0 + am;
    // B loader mapping: n4 = tid&31 (float4 col), kb = tid>>5 (0..7), 2 iters
    const int bn4 = tid & 31;
    const int bk  = tid >> 5;
    // W1 row for this thread's B columns: cols [bn4*4, bn4*4+4) are in half (bn4>=16)
    const int bhalf = bn4 >> 4;                  // 0 or 1
    const int bcol  = (bn4 & 15) * 4;            // 0..60
    const long long brow_base = (long long)bhalf * 320;

    float4 rA0, rA1, rB0, rB1;
    float acc[8][8];
    #pragma unroll
    for (int i = 0; i < 8; i++)
        #pragma unroll
        for (int j = 0; j < 8; j++) acc[i][j] = 0.f;

    // helpers as lambdas (compile-time inlined)
    auto loadA = [&](int k0, float4& r0, float4& r1) {
        if (a_gm < N_NODES) {
            const float* p = &embed[(size_t)a_gm * EMB + k0 + ak];
            r0 = *reinterpret_cast<const float4*>(p);
            r1 = *reinterpret_cast<const float4*>(p + 4);
        } else {
            r0 = make_float4(0.f, 0.f, 0.f, 0.f);
            r1 = r0;
        }
    };
    auto loadB = [&](int k0, float4& r0, float4& r1) {
        r0 = *reinterpret_cast<const float4*>(&W1[(brow_base + k0 + bk) * 64 + bcol]);
        r1 = *reinterpret_cast<const float4*>(&W1[(brow_base + k0 + bk + 8) * 64 + bcol]);
    };
    auto stsA = [&](const float4& r0, const float4& r1) {
        As[ak + 0][am] = r0.x; As[ak + 1][am] = r0.y;
        As[ak + 2][am] = r0.z; As[ak + 3][am] = r0.w;
        As[ak + 4][am] = r1.x; As[ak + 5][am] = r1.y;
        As[ak + 6][am] = r1.z; As[ak + 7][am] = r1.w;
    };
    auto stsB = [&](const float4& r0, const float4& r1) {
        *reinterpret_cast<float4*>(&Bs[bk][bn4 * 4])     = r0;
        *reinterpret_cast<float4*>(&Bs[bk + 8][bn4 * 4]) = r1;
    };

    loadA(0, rA0, rA1);
    loadB(0, rB0, rB1);
    stsA(rA0, rA1);
    stsB(rB0, rB1);
    __syncthreads();

    for (int c = 0; c < NCHUNK; c++) {
        if (c + 1 < NCHUNK) {
            loadA((c + 1) * BK, rA0, rA1);
            loadB((c + 1) * BK, rB0, rB1);
        }

        #pragma unroll
        for (int k = 0; k < BK; k++) {
            float4 a0 = *reinterpret_cast<const float4*>(&As[k][wm * 32 + tm * 4]);
            float4 a1 = *reinterpret_cast<const float4*>(&As[k][wm * 32 + tm * 4 + 16]);
            float4 b0 = *reinterpret_cast<const float4*>(&Bs[k][wn * 64 + tn * 4]);
            float4 b1 = *reinterpret_cast<const float4*>(&Bs[k][wn * 64 + tn * 4 + 32]);
            float av[8] = {a0.x, a0.y, a0.z, a0.w, a1.x, a1.y, a1.z, a1.w};
            float bv[8] = {b0.x, b0.y, b0.z, b0.w, b1.x, b1.y, b1.z, b1.w};
            #pragma unroll
            for (int i = 0; i < 8; i++)
                #pragma unroll
                for (int j = 0; j < 8; j++)
                    acc[i][j] = fmaf(av[i], bv[j], acc[i][j]);
        }
        __syncthreads();
        if (c + 1 < NCHUNK) {
            stsA(rA0, rA1);
            stsB(rB0, rB1);
            __syncthreads();
        }
    }

    // ---- epilogue: 8 rows (4+4 split) x 8 cols (4+4 split) per thread ----
    #pragma unroll
    for (int i = 0; i < 8; i++) {
        int gm = m0 + wm * 32 + tm * 4 + (i & 3) + (i >> 2) * 16;
        if (gm < N_NODES) {
            float* dst = &g_P[(size_t)gm * NH + wn * 64 + tn * 4];
            float4 v0 = make_float4(acc[i][0], acc[i][1], acc[i][2], acc[i][3]);
            float4 v1 = make_float4(acc[i][4], acc[i][5], acc[i][6], acc[i][7]);
            *reinterpret_cast<float4*>(dst)      = v0;
            *reinterpret_cast<float4*>(dst + 32) = v1;
        }
    }
}

// ---------------------------------------------------------------------------
// Kernel 2: cvec[j] = b1[j] + embed[node_id] @ W1[640:960, j]   (exact fp32)
// ---------------------------------------------------------------------------
__global__ void cvec_kernel(const float* __restrict__ embed,
                            const float* __restrict__ W1,
                            const float* __restrict__ b1,
                            const int*   __restrict__ nid) {
    int j = threadIdx.x;
    int n = nid[0];
    const float* er = &embed[(size_t)n * EMB];
    float s = b1[j];
    #pragma unroll 4
    for (int k = 0; k < EMB; k++)
        s = fmaf(er[k], W1[(640 + k) * 64 + j], s);
    g_cvec[j] = s;
}

// ---------------------------------------------------------------------------
// Kernel 3: per-edge gate. 16 lanes per edge (2 edges/warp), float4 loads,
// grid-stride with cvec/W2 cached in registers.  (proven at 41.9us)
// ---------------------------------------------------------------------------
__global__ __launch_bounds__(256) void edge_kernel(const void* __restrict__ ei_raw,
                                                   const float* __restrict__ eps,
                                                   const float* __restrict__ W2,
                                                   const float* __restrict__ b2,
                                                   const float* __restrict__ tmp,
                                                   float* __restrict__ out) {
    const int lane = threadIdx.x & 31;
    const int sub  = lane >> 4;
    const int j    = lane & 15;
    const int warpGlobal = (blockIdx.x * blockDim.x + threadIdx.x) >> 5;
    const int nWarps = (gridDim.x * blockDim.x) >> 5;

    const float4 cv = *reinterpret_cast<const float4*>(&g_cvec[j * 4]);
    const float4 w2 = *reinterpret_cast<const float4*>(&W2[j * 4]);
    const float  b2v = b2[0];
    const float  inv_tmp = 1.f / tmp[0];
    const int    is64 = g_idx64;
    const long long* e64 = (const long long*)ei_raw;
    const int*       e32 = (const int*)ei_raw;

    for (int e = warpGlobal * 2 + sub; e < N_EDGES; e += nWarps * 2) {
        int col, row;
        if (is64) { col = (int)e64[e]; row = (int)e64[N_EDGES + e]; }
        else      { col = e32[e];      row = e32[N_EDGES + e]; }

        float4 pc = *reinterpret_cast<const float4*>(&g_P[(size_t)col * NH + j * 4]);
        float4 pr = *reinterpret_cast<const float4*>(&g_P[(size_t)row * NH + 64 + j * 4]);

        float h0 = fmaxf(pc.x + pr.x + cv.x, 0.f);
        float h1 = fmaxf(pc.y + pr.y + cv.y, 0.f);
        float h2 = fmaxf(pc.z + pr.z + cv.z, 0.f);
        float h3 = fmaxf(pc.w + pr.w + cv.w, 0.f);

        float p = fmaf(h0, w2.x, fmaf(h1, w2.y, fmaf(h2, w2.z, h3 * w2.w)));
        #pragma unroll
        for (int o = 8; o > 0; o >>= 1)
            p += __shfl_xor_sync(0xffffffffu, p, o);

        if (j == 0) {
            float w    = p + b2v;
            const float bias = 0.0001f;
            float ev   = eps[e] * (1.f - 2.f * bias) + bias;
            float gate = (logf(ev) - log1pf(-ev) + w) * inv_tmp;
            out[e]     = 1.f / (1.f + expf(-gate));
        }
    }
}

// ---------------------------------------------------------------------------
// Inputs: 0:x 1:embed 2:edge_index 3:node_id 4:tmp 5:eps 6:W1 7:b1 8:W2 9:b2
// ---------------------------------------------------------------------------
extern "C" void kernel_launch(void* const* d_in, const int* in_sizes, int n_in,
                              void* d_out, int out_size) {
    const float* embed = (const float*)d_in[1];
    const void*  ei    = d_in[2];
    const int*   nid   = (const int*)d_in[3];
    const float* tmp   = (const float*)d_in[4];
    const float* eps   = (const float*)d_in[5];
    const float* W1    = (const float*)d_in[6];
    const float* b1    = (const float*)d_in[7];
    const float* W2    = (const float*)d_in[8];
    const float* b2    = (const float*)d_in[9];
    float* out = (float*)d_out;

    detect_kernel<<<1, 1>>>((const int*)ei);
    gemm_kernel<<<(N_NODES + 127) / 128, 256>>>(embed, W1);
    cvec_kernel<<<1, 64>>>(embed, W1, b1, nid);
    edge_kernel<<<1184, 256>>>(ei, eps, W2, b2, tmp, out);
}